// round 1
// baseline (speedup 1.0000x reference)
#include <cuda_runtime.h>

// Tropical (max-plus) Gram matrix: H[i,j] = max_k (|W[i,k]| + |W[j,k]|)
// W: 2048 x 10000 fp32 (row-major), H: 2048 x 2048 fp32.
//
// Strategy:
//  - 128x128 output tile per CTA, 256 threads, 8x8 register micro-tile.
//  - Symmetry: only upper-triangular tile pairs (136 CTAs ~= 1 wave), mirror-write.
//  - K tiled by 8, double-buffered smem, abs() applied at smem-store time.
//  - Inner math: packed add.rn.f32x2 (A duplicated in smem so (a_i,a_i) pairs
//    load directly) + __vimax3_s32 over k-pairs (valid: all values >= 0, so
//    fp32 order == s32 bit order). ~1.1 instr per update vs 2 for naive.

constexpr int K_DIM  = 10000;
constexpr int N_DIM  = 2048;
constexpr int KT     = 8;                 // k-tile
constexpr int NKT    = K_DIM / KT;        // 1250
constexpr int TILE   = 128;
constexpr int NTILES = N_DIM / TILE;      // 16
constexpr int NBLOCKS = NTILES * (NTILES + 1) / 2;  // 136

constexpr int ASTR = 2 * TILE + 4;        // 260 floats, 16B-multiple stride, bank-shifted
constexpr int BSTR = TILE + 4;            // 132 floats

__device__ __forceinline__ unsigned long long add_f32x2(unsigned long long a,
                                                        unsigned long long b) {
    unsigned long long r;
    asm("add.rn.f32x2 %0, %1, %2;" : "=l"(r) : "l"(a), "l"(b));
    return r;
}
__device__ __forceinline__ int lo32(unsigned long long v) { return (int)(unsigned int)v; }
__device__ __forceinline__ int hi32(unsigned long long v) { return (int)(unsigned int)(v >> 32); }

__global__ void __launch_bounds__(256, 1)
tropical_gram_kernel(const float* __restrict__ W, float* __restrict__ H)
{
    __shared__ __align__(16) float As[2][KT][ASTR];  // duplicated: As[k][2i]=As[k][2i+1]=|A[i,k]|
    __shared__ __align__(16) float Bs[2][KT][BSTR];

    // blockIdx.x -> upper-triangular tile pair (ti <= tj)
    int rem = (int)blockIdx.x;
    int ti = 0;
    while (rem >= NTILES - ti) { rem -= NTILES - ti; ++ti; }
    const int tj = ti + rem;

    const int tid  = (int)threadIdx.x;
    const int tx   = tid & 15;        // 0..15 -> j micro-tile
    const int ty   = tid >> 4;        // 0..15 -> i micro-tile
    const int lrow = tid >> 1;        // 0..127: row within tile for loading
    const int lc4  = (tid & 1) << 2;  // 0 or 4: float4 column within k-tile

    const float* Aptr = W + (size_t)(ti * TILE + lrow) * K_DIM + lc4;
    const float* Bptr = W + (size_t)(tj * TILE + lrow) * K_DIM + lc4;

    int acc[8][8];   // fp32 bit patterns, all values >= 0 so int max == float max
#pragma unroll
    for (int i = 0; i < 8; ++i)
#pragma unroll
        for (int j = 0; j < 8; ++j) acc[i][j] = 0;

    // ---- prefetch + store k-tile 0 ----
    float4 av = *(const float4*)Aptr;
    float4 bv = *(const float4*)Bptr;
    {
        float a0 = fabsf(av.x), a1 = fabsf(av.y), a2 = fabsf(av.z), a3 = fabsf(av.w);
        *(float2*)&As[0][lc4 + 0][2 * lrow] = make_float2(a0, a0);
        *(float2*)&As[0][lc4 + 1][2 * lrow] = make_float2(a1, a1);
        *(float2*)&As[0][lc4 + 2][2 * lrow] = make_float2(a2, a2);
        *(float2*)&As[0][lc4 + 3][2 * lrow] = make_float2(a3, a3);
        Bs[0][lc4 + 0][lrow] = fabsf(bv.x);
        Bs[0][lc4 + 1][lrow] = fabsf(bv.y);
        Bs[0][lc4 + 2][lrow] = fabsf(bv.z);
        Bs[0][lc4 + 3][lrow] = fabsf(bv.w);
    }
    __syncthreads();

    int buf = 0;
#pragma unroll 1
    for (int t = 0; t < NKT; ++t) {
        // prefetch next k-tile (global -> regs) while computing current
        if (t + 1 < NKT) {
            av = *(const float4*)(Aptr + (size_t)(t + 1) * KT);
            bv = *(const float4*)(Bptr + (size_t)(t + 1) * KT);
        }

#pragma unroll
        for (int k = 0; k < KT; k += 2) {
            const float* ap0 = &As[buf][k][ty * 16];
            const float* ap1 = &As[buf][k + 1][ty * 16];
            const float* bq0 = &Bs[buf][k][tx * 8];
            const float* bq1 = &Bs[buf][k + 1][tx * 8];

            ulonglong2 aA = *(const ulonglong2*)(ap0);
            ulonglong2 aB = *(const ulonglong2*)(ap0 + 4);
            ulonglong2 aC = *(const ulonglong2*)(ap0 + 8);
            ulonglong2 aD = *(const ulonglong2*)(ap0 + 12);
            ulonglong2 aE = *(const ulonglong2*)(ap1);
            ulonglong2 aF = *(const ulonglong2*)(ap1 + 4);
            ulonglong2 aG = *(const ulonglong2*)(ap1 + 8);
            ulonglong2 aH = *(const ulonglong2*)(ap1 + 12);

            unsigned long long a0[8] = {aA.x, aA.y, aB.x, aB.y, aC.x, aC.y, aD.x, aD.y};
            unsigned long long a1[8] = {aE.x, aE.y, aF.x, aF.y, aG.x, aG.y, aH.x, aH.y};

            ulonglong2 b00 = *(const ulonglong2*)(bq0);
            ulonglong2 b01 = *(const ulonglong2*)(bq0 + 4);
            ulonglong2 b10 = *(const ulonglong2*)(bq1);
            ulonglong2 b11 = *(const ulonglong2*)(bq1 + 4);

            unsigned long long b0[4] = {b00.x, b00.y, b01.x, b01.y};
            unsigned long long b1[4] = {b10.x, b10.y, b11.x, b11.y};

#pragma unroll
            for (int i = 0; i < 8; ++i) {
#pragma unroll
                for (int jp = 0; jp < 4; ++jp) {
                    unsigned long long s0 = add_f32x2(a0[i], b0[jp]);  // k
                    unsigned long long s1 = add_f32x2(a1[i], b1[jp]);  // k+1
                    acc[i][2 * jp]     = __vimax3_s32(acc[i][2 * jp],     lo32(s0), lo32(s1));
                    acc[i][2 * jp + 1] = __vimax3_s32(acc[i][2 * jp + 1], hi32(s0), hi32(s1));
                }
            }
        }

        if (t + 1 < NKT) {
            const int nb = buf ^ 1;
            float a0 = fabsf(av.x), a1 = fabsf(av.y), a2 = fabsf(av.z), a3 = fabsf(av.w);
            *(float2*)&As[nb][lc4 + 0][2 * lrow] = make_float2(a0, a0);
            *(float2*)&As[nb][lc4 + 1][2 * lrow] = make_float2(a1, a1);
            *(float2*)&As[nb][lc4 + 2][2 * lrow] = make_float2(a2, a2);
            *(float2*)&As[nb][lc4 + 3][2 * lrow] = make_float2(a3, a3);
            Bs[nb][lc4 + 0][lrow] = fabsf(bv.x);
            Bs[nb][lc4 + 1][lrow] = fabsf(bv.y);
            Bs[nb][lc4 + 2][lrow] = fabsf(bv.z);
            Bs[nb][lc4 + 3][lrow] = fabsf(bv.w);
            __syncthreads();
            buf = nb;
        }
    }

    // ---- epilogue: write tile (and mirror for off-diagonal) ----
    const int gi = ti * TILE + ty * 8;
    const int gj = tj * TILE + tx * 8;
#pragma unroll
    for (int i = 0; i < 8; ++i) {
        float4 v0 = make_float4(__int_as_float(acc[i][0]), __int_as_float(acc[i][1]),
                                __int_as_float(acc[i][2]), __int_as_float(acc[i][3]));
        float4 v1 = make_float4(__int_as_float(acc[i][4]), __int_as_float(acc[i][5]),
                                __int_as_float(acc[i][6]), __int_as_float(acc[i][7]));
        *(float4*)&H[(size_t)(gi + i) * N_DIM + gj]     = v0;
        *(float4*)&H[(size_t)(gi + i) * N_DIM + gj + 4] = v1;
    }
    if (ti != tj) {
#pragma unroll
        for (int j = 0; j < 8; ++j) {
            float4 v0 = make_float4(__int_as_float(acc[0][j]), __int_as_float(acc[1][j]),
                                    __int_as_float(acc[2][j]), __int_as_float(acc[3][j]));
            float4 v1 = make_float4(__int_as_float(acc[4][j]), __int_as_float(acc[5][j]),
                                    __int_as_float(acc[6][j]), __int_as_float(acc[7][j]));
            *(float4*)&H[(size_t)(gj + j) * N_DIM + gi]     = v0;
            *(float4*)&H[(size_t)(gj + j) * N_DIM + gi + 4] = v1;
        }
    }
}

extern "C" void kernel_launch(void* const* d_in, const int* in_sizes, int n_in,
                              void* d_out, int out_size) {
    const float* W = (const float*)d_in[0];
    float* H = (float*)d_out;
    tropical_gram_kernel<<<NBLOCKS, 256>>>(W, H);
}